// round 4
// baseline (speedup 1.0000x reference)
#include <cuda_runtime.h>
#include <math.h>
#include <stdint.h>

#define BB  2
#define SS  2048
#define DM  1024
#define NH  16
#define DKK 64

// Scratch (allocation-free rule: __device__ globals)
__device__ float g_Qh[BB*NH*SS*DKK];   // [b][h][s][dk]
__device__ float g_Kh[BB*NH*SS*DKK];
__device__ float g_Vh[BB*NH*SS*DKK];
__device__ float g_Oh[BB*SS*DM];       // [b][s][h*64+dk]

// ---------------------------------------------------------------------------
// tf32 / cp.async helpers
// ---------------------------------------------------------------------------
__device__ __forceinline__ uint32_t f2tf(float x) {
    uint32_t u;
    asm("cvt.rna.tf32.f32 %0, %1;" : "=r"(u) : "f"(x));
    return u;
}

__device__ __forceinline__ void mma_tf32(float c[4], const uint32_t a[4], const uint32_t b[2]) {
    asm volatile(
        "mma.sync.aligned.m16n8k8.row.col.f32.tf32.tf32.f32 "
        "{%0,%1,%2,%3}, {%4,%5,%6,%7}, {%8,%9}, {%0,%1,%2,%3};\n"
        : "+f"(c[0]), "+f"(c[1]), "+f"(c[2]), "+f"(c[3])
        : "r"(a[0]), "r"(a[1]), "r"(a[2]), "r"(a[3]), "r"(b[0]), "r"(b[1]));
}

__device__ __forceinline__ void cp16(float* dst, const float* src) {
    uint32_t d = (uint32_t)__cvta_generic_to_shared(dst);
    asm volatile("cp.async.cg.shared.global [%0], [%1], 16;" :: "r"(d), "l"(src));
}
__device__ __forceinline__ void cp_commit() {
    asm volatile("cp.async.commit_group;");
}
__device__ __forceinline__ void cp_wait1() {
    asm volatile("cp.async.wait_group 1;");
}

// ---------------------------------------------------------------------------
// tf32 tensor-core GEMM, cp.async double-buffered.
// Y[m][n] = sum_k X[m][k]*W[n][k] + bias[n]
// X: [M=4096,K=1024] rm, W: [N=1024,K=1024] rm.
// Block 128x128, BK=32, 256 threads (8 warps 4x2, warp tile 32x64).
// smem: raw fp32, tf32 cvt (RNA) at fragment load (identical numerics).
// ---------------------------------------------------------------------------
#define AS_OFF(buf) ((buf) * 4608)            // 128*36 floats
#define BS_OFF(buf) (9216 + (buf) * 4608)
#define GEMM_SMEM_BYTES (18432 * sizeof(float))   // 73728

__global__ __launch_bounds__(256, 2)
void gemm_tf32(const float* __restrict__ X, const float* __restrict__ W,
               const float* __restrict__ bias, float* __restrict__ Y,
               int head_split)
{
    extern __shared__ float sm[];

    const int bm = blockIdx.y * 128;
    const int bn = blockIdx.x * 128;
    const int tid = threadIdx.x;
    const int lane = tid & 31, wid = tid >> 5;
    const int wm = wid >> 1;        // 0..3
    const int wn = wid & 1;         // 0..1
    const int grp = lane >> 2;      // 0..7
    const int tig = lane & 3;       // 0..3

    const int ldrow = tid >> 3;     // 0..31
    const int ldc4  = tid & 7;

    float c[2][8][4];
    #pragma unroll
    for (int t = 0; t < 2; t++)
        #pragma unroll
        for (int u = 0; u < 8; u++)
            #pragma unroll
            for (int r = 0; r < 4; r++) c[t][u][r] = 0.f;

    // prologue: issue tile 0
    #pragma unroll
    for (int i = 0; i < 4; i++) {
        int row = ldrow + i * 32;
        cp16(&sm[AS_OFF(0) + row * 36 + ldc4 * 4], X + (size_t)(bm + row) * DM + ldc4 * 4);
        cp16(&sm[BS_OFF(0) + row * 36 + ldc4 * 4], W + (size_t)(bn + row) * DM + ldc4 * 4);
    }
    cp_commit();

    const int NT = DM / 32;   // 32
    for (int kt = 0; kt < NT; kt++) {
        if (kt + 1 < NT) {
            int k0n = (kt + 1) * 32;
            int bufn = (kt + 1) & 1;
            #pragma unroll
            for (int i = 0; i < 4; i++) {
                int row = ldrow + i * 32;
                cp16(&sm[AS_OFF(bufn) + row * 36 + ldc4 * 4], X + (size_t)(bm + row) * DM + k0n + ldc4 * 4);
                cp16(&sm[BS_OFF(bufn) + row * 36 + ldc4 * 4], W + (size_t)(bn + row) * DM + k0n + ldc4 * 4);
            }
        }
        cp_commit();
        cp_wait1();
        __syncthreads();

        const float* As = &sm[AS_OFF(kt & 1)];
        const float* Bs = &sm[BS_OFF(kt & 1)];

        #pragma unroll
        for (int s = 0; s < 4; s++) {
            uint32_t a[2][4];
            uint32_t b[8][2];
            const int cc = s * 8 + tig;
            #pragma unroll
            for (int t = 0; t < 2; t++) {
                int r = wm * 32 + t * 16 + grp;
                a[t][0] = f2tf(As[r * 36 + cc]);
                a[t][1] = f2tf(As[(r + 8) * 36 + cc]);
                a[t][2] = f2tf(As[r * 36 + cc + 4]);
                a[t][3] = f2tf(As[(r + 8) * 36 + cc + 4]);
            }
            #pragma unroll
            for (int u = 0; u < 8; u++) {
                int n = wn * 64 + u * 8 + grp;
                b[u][0] = f2tf(Bs[n * 36 + cc]);
                b[u][1] = f2tf(Bs[n * 36 + cc + 4]);
            }
            #pragma unroll
            for (int t = 0; t < 2; t++)
                #pragma unroll
                for (int u = 0; u < 8; u++)
                    mma_tf32(c[t][u], a[t], b[u]);
        }
        __syncthreads();   // before next iter's cp.async overwrites the other buffer
    }

    // epilogue
    #pragma unroll
    for (int t = 0; t < 2; t++) {
        #pragma unroll
        for (int u = 0; u < 8; u++) {
            int r0  = bm + wm * 32 + t * 16 + grp;
            int col = bn + wn * 64 + u * 8 + 2 * tig;
            float b0 = bias[col], b1 = bias[col + 1];
            #pragma unroll
            for (int half = 0; half < 2; half++) {
                int m = r0 + half * 8;
                float2 o;
                o.x = c[t][u][half * 2 + 0] + b0;
                o.y = c[t][u][half * 2 + 1] + b1;
                if (head_split) {
                    int b_ = m >> 11, s_ = m & 2047;
                    int h_ = col >> 6, dk = col & 63;
                    *(float2*)(Y + (((size_t)b_ * NH + h_) * SS + s_) * DKK + dk) = o;
                } else {
                    *(float2*)(Y + (size_t)m * DM + col) = o;
                }
            }
        }
    }
}

// ---------------------------------------------------------------------------
// Flash attention, tf32 mma, REGISTER-resident online softmax.
// Block: 128 threads (4 warps 2x2), tile Sq=64 x Sk=64, d_k=64.
// Ps: Q staging -> P(tf32).  KV: K(tf32) -> V(tf32).
// Row stats m/l/alpha in registers (dup across wn pair); cross-warp
// reduction via redm/reds[64][2].
// grid = (S/64, NH, B)
// ---------------------------------------------------------------------------
__global__ __launch_bounds__(128, 3)
void flash_attn_tc(const int* __restrict__ q_mask, const int* __restrict__ k_mask,
                   const int* __restrict__ causal_flag, int causal_default)
{
    __shared__ float Ps[64][68];
    __shared__ float KV[64][68];
    __shared__ float redm[64][2];
    __shared__ float reds[64][2];
    __shared__ int   kmask_s[64];

    const int b  = blockIdx.z, h = blockIdx.y;
    const int q0 = blockIdx.x * 64;
    const int tid = threadIdx.x;
    const int lane = tid & 31, wid = tid >> 5;
    const int wm = wid >> 1;      // 0..1 : q rows [wm*32, +32)
    const int wn = wid & 1;       // 0..1 : k cols / d cols [wn*32, +32)
    const int grp = lane >> 2;    // 0..7
    const int tig = lane & 3;     // 0..3
    const int causal = causal_flag ? causal_flag[0] : causal_default;

    const float* Qb = g_Qh + (((size_t)b * NH + h) * SS) * DKK;
    const float* Kb = g_Kh + (((size_t)b * NH + h) * SS) * DKK;
    const float* Vb = g_Vh + (((size_t)b * NH + h) * SS) * DKK;

    // ---- stage Q (raw fp32) into Ps ----
    #pragma unroll
    for (int i = 0; i < 8; i++) {
        int v = tid + i * 128;
        int row = v >> 4, c4 = v & 15;
        float4 d = *(const float4*)(Qb + (size_t)(q0 + row) * DKK + c4 * 4);
        *(float4*)&Ps[row][c4 * 4] = d;
    }
    __syncthreads();

    // ---- extract Q fragments (tf32, registers) ----
    uint32_t qf[8][2][4];
    #pragma unroll
    for (int s8 = 0; s8 < 8; s8++) {
        #pragma unroll
        for (int t = 0; t < 2; t++) {
            int r = wm * 32 + t * 16 + grp;
            int cc = s8 * 8 + tig;
            qf[s8][t][0] = f2tf(Ps[r    ][cc]);
            qf[s8][t][1] = f2tf(Ps[r + 8][cc]);
            qf[s8][t][2] = f2tf(Ps[r    ][cc + 4]);
            qf[s8][t][3] = f2tf(Ps[r + 8][cc + 4]);
        }
    }

    float o[2][4][4];
    #pragma unroll
    for (int t = 0; t < 2; t++)
        #pragma unroll
        for (int u = 0; u < 4; u++)
            #pragma unroll
            for (int r = 0; r < 4; r++) o[t][u][r] = 0.f;

    float m_r[2][2], l_r[2][2];
    #pragma unroll
    for (int t = 0; t < 2; t++)
        #pragma unroll
        for (int hf = 0; hf < 2; hf++) { m_r[t][hf] = -INFINITY; l_r[t][hf] = 0.f; }

    const int nkt = causal ? (q0 >> 6) + 1 : (SS / 64);

    for (int kt = 0; kt < nkt; kt++) {
        const int k0 = kt * 64;
        __syncthreads();   // S1: KV (prev V) + Ps (prev P / Q frags) free

        // ---- K tile (64x64 = 1024 float4) -> tf32 -> KV ; kmask ----
        #pragma unroll
        for (int i = 0; i < 8; i++) {
            int v = tid + i * 128;
            int row = v >> 4, c4 = v & 15;
            float4 d = *(const float4*)(Kb + (size_t)(k0 + row) * DKK + c4 * 4);
            float4 e;
            e.x = __uint_as_float(f2tf(d.x)); e.y = __uint_as_float(f2tf(d.y));
            e.z = __uint_as_float(f2tf(d.z)); e.w = __uint_as_float(f2tf(d.w));
            *(float4*)&KV[row][c4 * 4] = e;
        }
        if (tid < 64) kmask_s[tid] = k_mask[(size_t)b * SS + k0 + tid];
        __syncthreads();   // S2: K ready

        // ---- S = Q K^T via mma ----
        float sacc[2][4][4];
        #pragma unroll
        for (int t = 0; t < 2; t++)
            #pragma unroll
            for (int u = 0; u < 4; u++)
                #pragma unroll
                for (int r = 0; r < 4; r++) sacc[t][u][r] = 0.f;

        #pragma unroll
        for (int s8 = 0; s8 < 8; s8++) {
            uint32_t kb[4][2];
            const int cc = s8 * 8 + tig;
            #pragma unroll
            for (int u = 0; u < 4; u++) {
                int n = wn * 32 + u * 8 + grp;
                kb[u][0] = __float_as_uint(KV[n][cc]);
                kb[u][1] = __float_as_uint(KV[n][cc + 4]);
            }
            #pragma unroll
            for (int t = 0; t < 2; t++)
                #pragma unroll
                for (int u = 0; u < 4; u++)
                    mma_tf32(sacc[t][u], qf[s8][t], kb[u]);
        }

        // ---- scale + masks (registers) ----
        #pragma unroll
        for (int t = 0; t < 2; t++) {
            int rl0 = wm * 32 + t * 16 + grp;
            int qg0 = q0 + rl0, qg1 = qg0 + 8;
            #pragma unroll
            for (int u = 0; u < 4; u++) {
                int cl = wn * 32 + u * 8 + 2 * tig;
                int kg = k0 + cl;
                int km0 = kmask_s[cl], km1 = kmask_s[cl + 1];
                float x0 = sacc[t][u][0] * 0.125f;
                float x1 = sacc[t][u][1] * 0.125f;
                float x2 = sacc[t][u][2] * 0.125f;
                float x3 = sacc[t][u][3] * 0.125f;
                if ((causal && kg     > qg0) || km0 == 0) x0 = -INFINITY;
                if ((causal && kg + 1 > qg0) || km1 == 0) x1 = -INFINITY;
                if ((causal && kg     > qg1) || km0 == 0) x2 = -INFINITY;
                if ((causal && kg + 1 > qg1) || km1 == 0) x3 = -INFINITY;
                sacc[t][u][0] = x0; sacc[t][u][1] = x1;
                sacc[t][u][2] = x2; sacc[t][u][3] = x3;
            }
        }

        // ---- row max: per-thread partial + quad shuffle + cross-warp via smem ----
        #pragma unroll
        for (int t = 0; t < 2; t++) {
            #pragma unroll
            for (int hf = 0; hf < 2; hf++) {
                float mx = -INFINITY;
                #pragma unroll
                for (int u = 0; u < 4; u++)
                    mx = fmaxf(mx, fmaxf(sacc[t][u][2*hf], sacc[t][u][2*hf + 1]));
                mx = fmaxf(mx, __shfl_xor_sync(0xffffffffu, mx, 1));
                mx = fmaxf(mx, __shfl_xor_sync(0xffffffffu, mx, 2));
                if (tig == 0) redm[wm * 32 + t * 16 + grp + 8 * hf][wn] = mx;
            }
        }
        __syncthreads();   // S3: redm ready, all K reads done

        // ---- V tile (64x64 = 1024 float4) -> tf32 -> KV (overlaps exp phase) ----
        #pragma unroll
        for (int i = 0; i < 8; i++) {
            int v = tid + i * 128;
            int row = v >> 4, c4 = v & 15;
            float4 d = *(const float4*)(Vb + (size_t)(k0 + row) * DKK + c4 * 4);
            float4 e;
            e.x = __uint_as_float(f2tf(d.x)); e.y = __uint_as_float(f2tf(d.y));
            e.z = __uint_as_float(f2tf(d.z)); e.w = __uint_as_float(f2tf(d.w));
            *(float4*)&KV[row][c4 * 4] = e;
        }

        // ---- m_new, exp, row sums ----
        float mnew[2][2];
        #pragma unroll
        for (int t = 0; t < 2; t++) {
            #pragma unroll
            for (int hf = 0; hf < 2; hf++) {
                int rl = wm * 32 + t * 16 + grp + 8 * hf;
                float2 mm = *(float2*)&redm[rl][0];
                mnew[t][hf] = fmaxf(m_r[t][hf], fmaxf(mm.x, mm.y));
            }
        }
        float psum[2][2] = {{0.f, 0.f}, {0.f, 0.f}};
        #pragma unroll
        for (int t = 0; t < 2; t++) {
            #pragma unroll
            for (int u = 0; u < 4; u++) {
                float p0 = __expf(sacc[t][u][0] - mnew[t][0]);
                float p1 = __expf(sacc[t][u][1] - mnew[t][0]);
                float p2 = __expf(sacc[t][u][2] - mnew[t][1]);
                float p3 = __expf(sacc[t][u][3] - mnew[t][1]);
                sacc[t][u][0] = p0; sacc[t][u][1] = p1;
                sacc[t][u][2] = p2; sacc[t][u][3] = p3;
                psum[t][0] += p0 + p1;
                psum[t][1] += p2 + p3;
            }
        }
        #pragma unroll
        for (int t = 0; t < 2; t++) {
            #pragma unroll
            for (int hf = 0; hf < 2; hf++) {
                float s = psum[t][hf];
                s += __shfl_xor_sync(0xffffffffu, s, 1);
                s += __shfl_xor_sync(0xffffffffu, s, 2);
                if (tig == 0) reds[wm * 32 + t * 16 + grp + 8 * hf][wn] = s;
            }
        }

        // ---- write P (tf32) to Ps ----
        #pragma unroll
        for (int t = 0; t < 2; t++) {
            int rl0 = wm * 32 + t * 16 + grp;
            #pragma unroll
            for (int u = 0; u < 4; u++) {
                int cl = wn * 32 + u * 8 + 2 * tig;
                float2 lo, hi;
                lo.x = __uint_as_float(f2tf(sacc[t][u][0]));
                lo.y = __uint_as_float(f2tf(sacc[t][u][1]));
                hi.x = __uint_as_float(f2tf(sacc[t][u][2]));
                hi.y = __uint_as_float(f2tf(sacc[t][u][3]));
                *(float2*)&Ps[rl0    ][cl] = lo;
                *(float2*)&Ps[rl0 + 8][cl] = hi;
            }
        }
        __syncthreads();   // S4: V, reds, Ps all visible

        // ---- l/alpha update + rescale O (registers) ----
        float alpha_v[2][2];
        #pragma unroll
        for (int t = 0; t < 2; t++) {
            #pragma unroll
            for (int hf = 0; hf < 2; hf++) {
                int rl = wm * 32 + t * 16 + grp + 8 * hf;
                float2 ss = *(float2*)&reds[rl][0];
                float al = __expf(m_r[t][hf] - mnew[t][hf]);  // NaN iff both -inf (matches ref)
                l_r[t][hf] = l_r[t][hf] * al + ss.x + ss.y;
                m_r[t][hf] = mnew[t][hf];
                alpha_v[t][hf] = al;
            }
        }
        #pragma unroll
        for (int t = 0; t < 2; t++) {
            #pragma unroll
            for (int u = 0; u < 4; u++) {
                o[t][u][0] *= alpha_v[t][0]; o[t][u][1] *= alpha_v[t][0];
                o[t][u][2] *= alpha_v[t][1]; o[t][u][3] *= alpha_v[t][1];
            }
        }

        // ---- O += P @ V via mma ----
        #pragma unroll
        for (int s8 = 0; s8 < 8; s8++) {
            uint32_t pf[2][4];
            uint32_t vb[4][2];
            const int cc = s8 * 8 + tig;
            #pragma unroll
            for (int t = 0; t < 2; t++) {
                int r = wm * 32 + t * 16 + grp;
                pf[t][0] = __float_as_uint(Ps[r    ][cc]);
                pf[t][1] = __float_as_uint(Ps[r + 8][cc]);
                pf[t][2] = __float_as_uint(Ps[r    ][cc + 4]);
                pf[t][3] = __float_as_uint(Ps[r + 8][cc + 4]);
            }
            #pragma unroll
            for (int u = 0; u < 4; u++) {
                int dcol = wn * 32 + u * 8 + grp;
                int kr = s8 * 8 + tig;
                vb[u][0] = __float_as_uint(KV[kr    ][dcol]);
                vb[u][1] = __float_as_uint(KV[kr + 4][dcol]);
            }
            #pragma unroll
            for (int t = 0; t < 2; t++)
                #pragma unroll
                for (int u = 0; u < 4; u++)
                    mma_tf32(o[t][u], pf[t], vb[u]);
        }
    }

    // ---- epilogue: normalize, q_mask, write Oh ----
    #pragma unroll
    for (int t = 0; t < 2; t++) {
        #pragma unroll
        for (int hf = 0; hf < 2; hf++) {
            int rl = wm * 32 + t * 16 + grp + 8 * hf;
            int s_ = q0 + rl;
            int qm = q_mask[(size_t)b * SS + s_];
            float inv_l = 1.f / l_r[t][hf];   // NaN rows propagate (matches ref)
            #pragma unroll
            for (int u = 0; u < 4; u++) {
                int dcol = wn * 32 + u * 8 + 2 * tig;
                float2 ov;
                if (qm == 0) {
                    ov = make_float2(0.f, 0.f);
                } else {
                    ov.x = o[t][u][hf * 2 + 0] * inv_l;
                    ov.y = o[t][u][hf * 2 + 1] * inv_l;
                }
                *(float2*)(g_Oh + ((size_t)b * SS + s_) * DM + h * DKK + dcol) = ov;
            }
        }
    }
}

// ---------------------------------------------------------------------------
extern "C" void kernel_launch(void* const* d_in, const int* in_sizes, int n_in,
                              void* d_out, int out_size)
{
    const float* q  = (const float*)d_in[0];
    const float* k  = (const float*)d_in[1];
    const int*   qm = (const int*)  d_in[2];
    const int*   km = (const int*)  d_in[3];
    const float* Wq = (const float*)d_in[4];
    const float* bq = (const float*)d_in[5];
    const float* Wk = (const float*)d_in[6];
    const float* bk = (const float*)d_in[7];
    const float* Wv = (const float*)d_in[8];
    const float* bv = (const float*)d_in[9];
    const float* Wo = (const float*)d_in[10];
    const float* bo = (const float*)d_in[11];
    const int* causal = (n_in >= 13) ? (const int*)d_in[12] : nullptr;

    float *Qh, *Kh, *Vh, *Oh;
    cudaGetSymbolAddress((void**)&Qh, g_Qh);
    cudaGetSymbolAddress((void**)&Kh, g_Kh);
    cudaGetSymbolAddress((void**)&Vh, g_Vh);
    cudaGetSymbolAddress((void**)&Oh, g_Oh);

    cudaFuncSetAttribute(gemm_tf32, cudaFuncAttributeMaxDynamicSharedMemorySize,
                         (int)GEMM_SMEM_BYTES);

    dim3 gg(DM / 128, (BB * SS) / 128);   // (8, 32)
    gemm_tf32<<<gg, 256, GEMM_SMEM_BYTES>>>(q, Wq, bq, Qh, 1);
    gemm_tf32<<<gg, 256, GEMM_SMEM_BYTES>>>(k, Wk, bk, Kh, 1);
    gemm_tf32<<<gg, 256, GEMM_SMEM_BYTES>>>(k, Wv, bv, Vh, 1);

    dim3 ga(SS / 64, NH, BB);             // (32, 16, 2)
    flash_attn_tc<<<ga, 128>>>(qm, km, causal, 1);

    gemm_tf32<<<gg, 256, GEMM_SMEM_BYTES>>>(Oh, Wo, bo, (float*)d_out, 0);
}